// round 2
// baseline (speedup 1.0000x reference)
#include <cuda_runtime.h>
#include <cuda_bf16.h>

#define NB 128
#define NC 3
#define NH 256
#define NW 256
#define SHIFT 32
#define CUT_HALF 25                // cut=51 -> cut//2 = 25
#define PER_BATCH (NC * NH * NW)   // 196608
#define SPLITS 8

__device__ float g_partial[NB * SPLITS];
__device__ float g_mean[NB];

// ---------------- Pass 1: per-batch partial sums (float4, full-chip) ----------------
__global__ void __launch_bounds__(256) partial_sum_kernel(const float* __restrict__ x) {
    const int blk = blockIdx.x;           // 0 .. NB*SPLITS-1
    const int b   = blk >> 3;
    const int s   = blk & (SPLITS - 1);
    const int per = PER_BATCH / SPLITS;   // 24576 floats
    const float4* p = reinterpret_cast<const float4*>(x + (size_t)b * PER_BATCH + (size_t)s * per);
    const int n4 = per / 4;               // 6144 float4

    float acc = 0.f;
    #pragma unroll 4
    for (int i = threadIdx.x; i < n4; i += 256) {
        float4 v = p[i];
        acc += (v.x + v.y) + (v.z + v.w);
    }
    #pragma unroll
    for (int off = 16; off > 0; off >>= 1)
        acc += __shfl_down_sync(0xFFFFFFFFu, acc, off);
    __shared__ float smem[8];
    if ((threadIdx.x & 31) == 0) smem[threadIdx.x >> 5] = acc;
    __syncthreads();
    if (threadIdx.x < 8) {
        float v = smem[threadIdx.x];
        #pragma unroll
        for (int off = 4; off > 0; off >>= 1)
            v += __shfl_down_sync(0xFFu, v, off);
        if (threadIdx.x == 0) g_partial[blk] = v;
    }
}

// ---------------- Pass 1b: finalize means (tiny) ----------------
__global__ void finalize_mean_kernel() {
    int b = threadIdx.x;   // 128 threads
    float s = 0.f;
    #pragma unroll
    for (int i = 0; i < SPLITS; i++) s += g_partial[b * SPLITS + i];
    g_mean[b] = s * (1.0f / (float)PER_BATCH);
}

// ---------------- Pass 2: fused color + translate + cutout, 4 pixels/thread ----------------
__global__ void __launch_bounds__(256) diffaug_kernel(
    const float* __restrict__ x,
    const float* __restrict__ r_bright,
    const float* __restrict__ r_sat,
    const float* __restrict__ r_con,
    const int*   __restrict__ t_x,
    const int*   __restrict__ t_y,
    const int*   __restrict__ off_x,
    const int*   __restrict__ off_y,
    float* __restrict__ out)
{
    // tid over NB*NH*(NW/4): each thread does 4 consecutive w
    const int tid = blockIdx.x * 256 + threadIdx.x;
    const int w0  = (tid & (NW / 4 - 1)) << 2;        // 0,4,...,252
    const int h   = (tid >> 6) & (NH - 1);
    const int b   = tid >> 14;

    const int tx = t_x[b] - SHIFT;
    const int ty = t_y[b] - SHIFT;
    const int ox = off_x[b];
    const int oy = off_y[b];

    const int sh = h + tx;
    const bool row_oob = (unsigned)sh >= (unsigned)NH;
    const bool row_cut = (h >= ox - CUT_HALF) & (h <= ox + CUT_HALF);

    const size_t plane = (size_t)NH * NW;
    const size_t obase = (size_t)b * PER_BATCH + (size_t)h * NW + w0;

    const float br = r_bright[b] - 0.5f;
    const float s  = r_sat[b] * 2.0f;
    const float cc = r_con[b] + 0.5f;
    const float M  = g_mean[b];
    const float a  = s * cc;
    // out_c = x_c*a + k,  k = (m - M)*cc + M + br - m*a  (m = per-pixel channel mean)
    const float kbase = M * (1.0f - cc) + br;          // k = m*(cc - a) + kbase

    float4 o0, o1, o2;
    float* po0 = &o0.x; float* po1 = &o1.x; float* po2 = &o2.x;

    const size_t irow = (size_t)b * PER_BATCH + (size_t)sh * NW;

    #pragma unroll
    for (int i = 0; i < 4; i++) {
        const int w  = w0 + i;
        const int sw = w + ty;
        const bool zero = row_oob | ((unsigned)sw >= (unsigned)NW)
                        | (row_cut & (w >= oy - CUT_HALF) & (w <= oy + CUT_HALF));
        if (zero) {
            po0[i] = 0.f; po1[i] = 0.f; po2[i] = 0.f;
        } else {
            const size_t ib = irow + sw;
            const float x0 = x[ib];
            const float x1 = x[ib + plane];
            const float x2 = x[ib + 2 * plane];
            const float m  = (x0 + x1 + x2) * (1.0f / 3.0f);
            const float k  = fmaf(m, cc - a, kbase);
            po0[i] = fmaf(x0, a, k);
            po1[i] = fmaf(x1, a, k);
            po2[i] = fmaf(x2, a, k);
        }
    }

    *reinterpret_cast<float4*>(out + obase)             = o0;
    *reinterpret_cast<float4*>(out + obase + plane)     = o1;
    *reinterpret_cast<float4*>(out + obase + 2 * plane) = o2;
}

extern "C" void kernel_launch(void* const* d_in, const int* in_sizes, int n_in,
                              void* d_out, int out_size) {
    const float* x        = (const float*)d_in[0];
    const float* r_bright = (const float*)d_in[1];
    const float* r_sat    = (const float*)d_in[2];
    const float* r_con    = (const float*)d_in[3];
    const int*   t_x      = (const int*)d_in[4];
    const int*   t_y      = (const int*)d_in[5];
    const int*   off_x    = (const int*)d_in[6];
    const int*   off_y    = (const int*)d_in[7];
    float* out = (float*)d_out;

    partial_sum_kernel<<<NB * SPLITS, 256>>>(x);
    finalize_mean_kernel<<<1, 128>>>();
    diffaug_kernel<<<(NB * NH * (NW / 4)) / 256, 256>>>(
        x, r_bright, r_sat, r_con, t_x, t_y, off_x, off_y, out);
}